// round 17
// baseline (speedup 1.0000x reference)
#include <cuda_runtime.h>
#include <cstdint>

// Dequant: groups of 17 int32 (16 "byte" ints -> 32 nibbles, 1 scale int).
// out[g*32 + i] = (nibble_i - 8) / 12 * exp2(clamp(scale-127, -126, 127))
//
// Engine-driven with split-phase pipeline: input arrives as TWO 4352 B bulk
// loads on separate mbarriers; each 64-group half is dequanted and emitted
// as an 8 KB bulk store as soon as it lands. Half-1 load overlaps half-0
// compute; half-0 store overlaps half-1 compute.

#define THREADS 256
#define GROUPS_PER_BLOCK 128
#define INTS_PER_BLOCK   (GROUPS_PER_BLOCK * 17)   // 2176
#define IN_BYTES         (INTS_PER_BLOCK * 4)      // 8704
#define HALF_IN_INTS     (INTS_PER_BLOCK / 2)      // 1088 (64 groups)
#define HALF_IN_BYTES    (HALF_IN_INTS * 4)        // 4352 (16B multiple)
#define QUADS_PER_BLOCK  (GROUPS_PER_BLOCK * 8)    // 1024
#define OUT_BYTES        (QUADS_PER_BLOCK * 16)    // 16384
#define HALF_QUADS       (QUADS_PER_BLOCK / 2)     // 512
#define HALF_OUT_BYTES   (OUT_BYTES / 2)           // 8192

__device__ __forceinline__ uint32_t smem_u32(const void* p) {
    uint32_t a;
    asm("{ .reg .u64 t; cvta.to.shared.u64 t, %1; cvt.u32.u64 %0, t; }"
        : "=r"(a) : "l"(p));
    return a;
}

__device__ __forceinline__ void mbar_wait0(uint32_t mbar_addr) {
    uint32_t done;
    asm volatile(
        "{\n\t.reg .pred p;\n\t"
        "mbarrier.try_wait.parity.acquire.cta.shared::cta.b64 p, [%1], %2;\n\t"
        "selp.b32 %0, 1, 0, p;\n\t}"
        : "=r"(done) : "r"(mbar_addr), "r"(0u) : "memory");
    if (!done) {
        asm volatile(
            "{\n\t.reg .pred P1;\n"
            "WAIT_LOOP_%=:\n\t"
            "mbarrier.try_wait.parity.acquire.cta.shared::cta.b64 P1, [%0], %1, 0x989680;\n\t"
            "@P1 bra.uni WAIT_DONE_%=;\n\t"
            "bra.uni WAIT_LOOP_%=;\n"
            "WAIT_DONE_%=:\n\t}"
            :: "r"(mbar_addr), "r"(0u) : "memory");
    }
}

__global__ void __launch_bounds__(THREADS) dequant_mxfp4_kernel(
    const int* __restrict__ packed,
    float4* __restrict__ out)
{
    __shared__ alignas(16) int    sm_in[INTS_PER_BLOCK];
    __shared__ alignas(16) float4 sm_out[QUADS_PER_BLOCK];
    __shared__ alignas(8) uint64_t mbar[2];

    uint32_t in_addr   = smem_u32(sm_in);
    uint32_t out_addr  = smem_u32(sm_out);
    uint32_t mbar0 = smem_u32(&mbar[0]);
    uint32_t mbar1 = smem_u32(&mbar[1]);

    if (threadIdx.x == 0) {
        asm volatile("mbarrier.init.shared.b64 [%0], 1;" :: "r"(mbar0) : "memory");
        asm volatile("mbarrier.init.shared.b64 [%0], 1;" :: "r"(mbar1) : "memory");
    }
    __syncthreads();

    if (threadIdx.x == 0) {
        asm volatile("fence.proxy.async.shared::cta;" ::: "memory");
        const char* src = (const char*)packed + (size_t)blockIdx.x * IN_BYTES;
        asm volatile("mbarrier.arrive.expect_tx.shared.b64 _, [%0], %1;"
                     :: "r"(mbar0), "r"((uint32_t)HALF_IN_BYTES) : "memory");
        asm volatile(
            "cp.async.bulk.shared::cta.global.mbarrier::complete_tx::bytes "
            "[%0], [%1], %2, [%3];"
            :: "r"(in_addr), "l"(src), "r"((uint32_t)HALF_IN_BYTES), "r"(mbar0)
            : "memory");
        asm volatile("mbarrier.arrive.expect_tx.shared.b64 _, [%0], %1;"
                     :: "r"(mbar1), "r"((uint32_t)HALF_IN_BYTES) : "memory");
        asm volatile(
            "cp.async.bulk.shared::cta.global.mbarrier::complete_tx::bytes "
            "[%0], [%1], %2, [%3];"
            :: "r"(in_addr + HALF_IN_BYTES), "l"(src + HALF_IN_BYTES),
               "r"((uint32_t)HALF_IN_BYTES), "r"(mbar1)
            : "memory");
    }

    char* dst = (char*)out + (size_t)blockIdx.x * OUT_BYTES;

    #pragma unroll
    for (int h = 0; h < 2; h++) {
        mbar_wait0(h == 0 ? mbar0 : mbar1);

        const int* in = sm_in + h * HALF_IN_INTS;

        #pragma unroll
        for (int j = 0; j < 2; j++) {
            int lq  = threadIdx.x + j * THREADS;   // 0..511 within half
            int lg  = lq >> 3;
            int sub = lq & 7;
            int base = lg * 17;

            int v0 = in[base + sub * 2];
            int v1 = in[base + sub * 2 + 1];
            int s  = in[base + 16];

            // exp2(clip(s-127,-126,127)) == float with exponent clamp(s,1,254)
            int e = min(max(s, 1), 254);
            float scale = __int_as_float(e << 23) * (1.0f / 12.0f);

            float4 r;
            r.x = (float)((v0 & 15)        - 8) * scale;
            r.y = (float)(((v0 >> 4) & 15) - 8) * scale;
            r.z = (float)((v1 & 15)        - 8) * scale;
            r.w = (float)(((v1 >> 4) & 15) - 8) * scale;

            sm_out[h * HALF_QUADS + lq] = r;
        }
        __syncthreads();

        if (threadIdx.x == 0) {
            asm volatile("fence.proxy.async.shared::cta;" ::: "memory");
            asm volatile(
                "cp.async.bulk.global.shared::cta.bulk_group [%0], [%1], %2;"
                :: "l"(dst + h * HALF_OUT_BYTES),
                   "r"(out_addr + h * HALF_OUT_BYTES),
                   "r"((uint32_t)HALF_OUT_BYTES)
                : "memory");
            asm volatile("cp.async.bulk.commit_group;" ::: "memory");
        }
    }

    // Tail: smem must stay valid until both store reads drain.
    if (threadIdx.x == 0) {
        asm volatile("cp.async.bulk.wait_group.read 0;" ::: "memory");
    }
}

extern "C" void kernel_launch(void* const* d_in, const int* in_sizes, int n_in,
                              void* d_out, int out_size)
{
    const int* packed = (const int*)d_in[0];
    float4* out = (float4*)d_out;

    int num_quads = out_size / 4;                    // 33,554,432
    int blocks = num_quads / QUADS_PER_BLOCK;        // 32768 (exact)

    dequant_mxfp4_kernel<<<blocks, THREADS>>>(packed, out);
}